// round 2
// baseline (speedup 1.0000x reference)
#include <cuda_runtime.h>
#include <cuda_bf16.h>
#include <math.h>
#include <stdint.h>

// Problem constants
#define HB 512
#define SB 4096
#define BB 32

// Logits-GEMM tiling
#define MTILE 128          // rows of flattened (b,s) per CTA
#define NCHUNK 128         // output-column chunk held in registers
#define KBLK 64            // K staging block for Wr
#define XLDA 520           // padded smem row stride for X (bf16) -> conflict-free
#define WLDA 72            // padded smem row stride for Wr chunk (bf16)

// dynamic smem bytes for k_logits
#define K1_SMEM ((128*XLDA + 128*WLDA)*2 + (512+512+128)*4)

// ---------------- scratch (__device__ globals; no allocation) ----------------
__device__ float          g_qb[BB*HB];        // q@Wq^T + bq + br
__device__ __nv_bfloat16  g_Wrb[HB*HB];       // Wr in bf16
__device__ float          g_logits[BB*SB];
__device__ float          g_weights[BB*SB];
__device__ float          g_partial[BB*8*HB]; // weighted-ref partial sums

// ---------------- Wr -> bf16 ----------------
__global__ void k_conv(const float* __restrict__ Wr) {
    int i = blockIdx.x * 256 + threadIdx.x;   // grid 1024 * 256 = 262144
    g_Wrb[i] = __float2bfloat16_rn(Wr[i]);
}

// ---------------- qb[b,h] = dot(query[b,:], Wq[h,:]) + bq[h] + br[h] ----------------
__global__ void k_qb(const float* __restrict__ query, const float* __restrict__ Wq,
                     const float* __restrict__ bq, const float* __restrict__ br) {
    int b = blockIdx.x, tid = threadIdx.x;    // 32 blocks, 512 threads
    __shared__ float qs[HB];
    qs[tid] = query[b*HB + tid];
    __syncthreads();
    float a = bq[tid] + br[tid];
    const float* wq = Wq + (size_t)tid * HB;
    #pragma unroll 8
    for (int k = 0; k < HB; ++k) a += qs[k] * wq[k];
    g_qb[b*HB + tid] = a;
}

// ---------------- fused logits: bf16 mma.sync GEMM + tanh reduction ----------------
__global__ void __launch_bounds__(256, 1)
k_logits(const float* __restrict__ ref, const float* __restrict__ V) {
    extern __shared__ char smem[];
    __nv_bfloat16* Xs  = (__nv_bfloat16*)smem;          // [128][XLDA]
    __nv_bfloat16* Ws  = Xs + 128*XLDA;                 // [128][WLDA]
    float* tbs  = (float*)(Ws + 128*WLDA);              // q[b,:]+br  (512)
    float* Vs   = tbs + HB;                             // V          (512)
    float* lsum = Vs + HB;                              // logits     (128)

    const int tid  = threadIdx.x;
    const int lane = tid & 31, warp = tid >> 5;
    const int wm = warp & 3;      // row group: 32*wm
    const int wn = warp >> 2;     // col group within chunk: 64*wn

    const long row0 = (long)blockIdx.x * MTILE;         // global flattened row
    const int  b    = (int)(row0 >> 12);                // row0 / 4096

    // Load X tile (128 x 512 fp32) -> bf16 smem, float4-coalesced
    const float4* Xg = (const float4*)(ref + row0 * HB);
    #pragma unroll 4
    for (int i = tid; i < 128*128; i += 256) {          // 128 float4 per row
        int r = i >> 7, c4 = i & 127;
        float4 v = Xg[r*128 + c4];
        __nv_bfloat162* dst = (__nv_bfloat162*)&Xs[r*XLDA + c4*4];
        dst[0] = __floats2bfloat162_rn(v.x, v.y);
        dst[1] = __floats2bfloat162_rn(v.z, v.w);
    }
    for (int i = tid; i < HB; i += 256) { tbs[i] = g_qb[b*HB + i]; Vs[i] = V[i]; }
    if (tid < MTILE) lsum[tid] = 0.f;

    for (int nc = 0; nc < 4; ++nc) {                    // 4 chunks of 128 cols
        float acc[2][8][4];
        #pragma unroll
        for (int mt = 0; mt < 2; ++mt)
            #pragma unroll
            for (int nt = 0; nt < 8; ++nt)
                #pragma unroll
                for (int i = 0; i < 4; ++i) acc[mt][nt][i] = 0.f;

        for (int kb = 0; kb < HB; kb += KBLK) {
            __syncthreads();                            // protect Ws reuse (& initial loads)
            // stage Wr chunk: rows nc*128..+127, cols kb..kb+63 (bf16, 16B vectors)
            #pragma unroll
            for (int i = tid; i < 128*8; i += 256) {
                int n = i >> 3, c8 = i & 7;
                const uint4* src = (const uint4*)(g_Wrb + (((size_t)(nc*128 + n)) << 9) + kb + c8*8);
                *(uint4*)&Ws[n*WLDA + c8*8] = *src;
            }
            __syncthreads();

            #pragma unroll
            for (int kk = 0; kk < KBLK; kk += 16) {
                // A fragments (reused across the 8 n-tiles)
                uint32_t a[2][4];
                const int ar = wm*32 + (lane >> 2);
                const int ac = kb + kk + ((lane & 3) << 1);
                #pragma unroll
                for (int mt = 0; mt < 2; ++mt) {
                    const __nv_bfloat16* p = &Xs[(ar + mt*16)*XLDA + ac];
                    a[mt][0] = *(const uint32_t*)(p);
                    a[mt][1] = *(const uint32_t*)(p + 8*XLDA);
                    a[mt][2] = *(const uint32_t*)(p + 8);
                    a[mt][3] = *(const uint32_t*)(p + 8*XLDA + 8);
                }
                #pragma unroll
                for (int nt = 0; nt < 8; ++nt) {
                    const int bn = wn*64 + nt*8 + (lane >> 2);
                    const __nv_bfloat16* q = &Ws[bn*WLDA + kk + ((lane & 3) << 1)];
                    uint32_t b0 = *(const uint32_t*)(q);
                    uint32_t b1 = *(const uint32_t*)(q + 8);
                    #pragma unroll
                    for (int mt = 0; mt < 2; ++mt) {
                        asm volatile(
                            "mma.sync.aligned.m16n8k16.row.col.f32.bf16.bf16.f32 "
                            "{%0,%1,%2,%3}, {%4,%5,%6,%7}, {%8,%9}, {%0,%1,%2,%3};\n"
                            : "+f"(acc[mt][nt][0]), "+f"(acc[mt][nt][1]),
                              "+f"(acc[mt][nt][2]), "+f"(acc[mt][nt][3])
                            : "r"(a[mt][0]), "r"(a[mt][1]), "r"(a[mt][2]), "r"(a[mt][3]),
                              "r"(b0), "r"(b1));
                    }
                }
            }
        }

        // epilogue: logits += V[n] * tanh(r + q[b,n] + br[n]) over this chunk
        float rs[2][2] = {{0.f,0.f},{0.f,0.f}};
        #pragma unroll
        for (int mt = 0; mt < 2; ++mt)
            #pragma unroll
            for (int nt = 0; nt < 8; ++nt) {
                const int col0 = nc*128 + wn*64 + nt*8 + ((lane & 3) << 1);
                #pragma unroll
                for (int i = 0; i < 4; ++i) {
                    const int col = col0 + (i & 1);
                    float t = tanhf(acc[mt][nt][i] + tbs[col]);
                    rs[mt][i >> 1] += t * Vs[col];
                }
            }
        #pragma unroll
        for (int mt = 0; mt < 2; ++mt)
            #pragma unroll
            for (int h = 0; h < 2; ++h) {
                float v = rs[mt][h];
                v += __shfl_xor_sync(0xffffffffu, v, 1);
                v += __shfl_xor_sync(0xffffffffu, v, 2);
                if ((lane & 3) == 0)
                    atomicAdd(&lsum[wm*32 + mt*16 + h*8 + (lane >> 2)], v);
            }
    }

    __syncthreads();
    if (tid < MTILE) g_logits[row0 + tid] = lsum[tid];
}

// ---------------- softmax over S per batch ----------------
__global__ void k_softmax() {
    const int b = blockIdx.x, tid = threadIdx.x;        // 32 blocks, 256 threads
    __shared__ float red[256];
    const float* l = g_logits + b*SB;
    float m = -1e30f;
    for (int i = tid; i < SB; i += 256) m = fmaxf(m, l[i]);
    red[tid] = m; __syncthreads();
    for (int s = 128; s; s >>= 1) { if (tid < s) red[tid] = fmaxf(red[tid], red[tid+s]); __syncthreads(); }
    m = red[0]; __syncthreads();
    float sum = 0.f;
    for (int i = tid; i < SB; i += 256) sum += expf(l[i] - m);
    red[tid] = sum; __syncthreads();
    for (int s = 128; s; s >>= 1) { if (tid < s) red[tid] += red[tid+s]; __syncthreads(); }
    const float inv = 1.f / red[0];
    for (int i = tid; i < SB; i += 256) g_weights[b*SB + i] = expf(l[i] - m) * inv;
}

// ---------------- weighted ref sum (partials per 512-s chunk) ----------------
__global__ void k_wsum(const float* __restrict__ ref) {
    const int b = blockIdx.y, ch = blockIdx.x;          // (8, 32) grid, 256 threads
    const int tid = threadIdx.x;
    __shared__ float ws[512];
    for (int i = tid; i < 512; i += 256) ws[i] = g_weights[b*SB + ch*512 + i];
    __syncthreads();
    float a0 = 0.f, a1 = 0.f;
    const float* base = ref + ((size_t)b*SB + (size_t)ch*512) * HB;
    #pragma unroll 4
    for (int s = 0; s < 512; ++s) {
        const float wv = ws[s];
        a0 += wv * base[(size_t)s*HB + tid];
        a1 += wv * base[(size_t)s*HB + tid + 256];
    }
    g_partial[(b*8 + ch)*HB + tid]       = a0;
    g_partial[(b*8 + ch)*HB + tid + 256] = a1;
}

// ---------------- out[b,h] = (Σ partial)·Wr[h,:] + br[h] ----------------
__global__ void k_out(const float* __restrict__ Wr, const float* __restrict__ br,
                      float* __restrict__ out) {
    const int b = blockIdx.x, tid = threadIdx.x;        // 32 blocks, 512 threads
    __shared__ float accs[HB];
    float a = 0.f;
    #pragma unroll
    for (int c = 0; c < 8; ++c) a += g_partial[(b*8 + c)*HB + tid];
    accs[tid] = a; __syncthreads();
    float o = br[tid];
    const float* wr = Wr + (size_t)tid * HB;
    #pragma unroll 8
    for (int k = 0; k < HB; ++k) o += accs[k] * wr[k];
    out[b*HB + tid] = o;
}

// ---------------- launch ----------------
extern "C" void kernel_launch(void* const* d_in, const int* in_sizes, int n_in,
                              void* d_out, int out_size) {
    const float* query = (const float*)d_in[0];
    const float* ref   = (const float*)d_in[1];
    const float* Wq    = (const float*)d_in[2];
    const float* bq    = (const float*)d_in[3];
    const float* Wr    = (const float*)d_in[4];
    const float* br    = (const float*)d_in[5];
    const float* V     = (const float*)d_in[6];
    float* out = (float*)d_out;

    cudaFuncSetAttribute(k_logits, cudaFuncAttributeMaxDynamicSharedMemorySize, K1_SMEM);

    k_conv   <<<1024, 256>>>(Wr);
    k_qb     <<<BB, 512>>>(query, Wq, bq, br);
    k_logits <<<(BB*SB)/MTILE, 256, K1_SMEM>>>(ref, V);
    k_softmax<<<BB, 256>>>();
    k_wsum   <<<dim3(8, BB), 256>>>(ref);
    k_out    <<<BB, 512>>>(Wr, br, out);
}

// round 5
// speedup vs baseline: 1.2586x; 1.2586x over previous
#include <cuda_runtime.h>
#include <cuda_bf16.h>
#include <math.h>
#include <stdint.h>

#define HB 512
#define SB 4096
#define BB 32

// ---------------- k_logits smem layout ----------------
#define XLDA 520                       // bf16 elems per X row (padded)
#define WLDA 72                        // bf16 elems per B row (padded)
#define XS_OFF   0
#define XS_BYTES (128*XLDA*2)          // 133120
#define BS_OFF   XS_BYTES
#define BS_BYTES (128*WLDA*2)          // 18432 per buffer, x2
#define F_OFF    (BS_OFF + 2*BS_BYTES)
#define TBS_OFF  F_OFF                 // 512 floats: q[b,:]+bq+br
#define VS_OFF   (F_OFF + 2048)        // 512 floats: V
#define LSUM_OFF (F_OFF + 4096)        // 128 floats
#define K1_SMEM  (F_OFF + 4608)        // 174592 bytes

// ---------------- scratch ----------------
__device__ float          g_qb[BB*HB];
__device__ __nv_bfloat16  g_Wrb[HB*HB];
__device__ float          g_logits[BB*SB];
__device__ float          g_weights[BB*SB];
__device__ float          g_partial[BB*32*HB];

// ---------------- helpers ----------------
static __device__ __forceinline__ uint32_t s2u(const void* p) {
    uint32_t a;
    asm("{ .reg .u64 t; cvta.to.shared.u64 t, %1; cvt.u32.u64 %0, t; }" : "=r"(a) : "l"(p));
    return a;
}
static __device__ __forceinline__ float tanha(float x) {
    float y; asm("tanh.approx.f32 %0, %1;" : "=f"(y) : "f"(x)); return y;
}
#define LDSM4(r0,r1,r2,r3,a) \
    asm volatile("ldmatrix.sync.aligned.m8n8.x4.shared.b16 {%0,%1,%2,%3}, [%4];" \
                 : "=r"(r0),"=r"(r1),"=r"(r2),"=r"(r3) : "r"(a))
#define MMA16816(acc, a0,a1,a2,a3, b0,b1) \
    asm volatile("mma.sync.aligned.m16n8k16.row.col.f32.bf16.bf16.f32 " \
                 "{%0,%1,%2,%3}, {%4,%5,%6,%7}, {%8,%9}, {%0,%1,%2,%3};\n" \
                 : "+f"((acc)[0]), "+f"((acc)[1]), "+f"((acc)[2]), "+f"((acc)[3]) \
                 : "r"(a0), "r"(a1), "r"(a2), "r"(a3), "r"(b0), "r"(b1))
#define CPASYNC16(d, s) \
    asm volatile("cp.async.cg.shared.global [%0], [%1], 16;" :: "r"(d), "l"(s))

// ---------------- Wr -> bf16 ----------------
__global__ void k_conv(const float* __restrict__ Wr) {
    int i = blockIdx.x * 256 + threadIdx.x;
    g_Wrb[i] = __float2bfloat16_rn(Wr[i]);
}

// ---------------- qb[b,h] = query[b,:].Wq[h,:] + bq[h] + br[h] ----------------
__global__ void k_qb(const float* __restrict__ query, const float* __restrict__ Wq,
                     const float* __restrict__ bq, const float* __restrict__ br) {
    int b = blockIdx.x, tid = threadIdx.x;    // 32 x 512
    __shared__ float qs[HB];
    qs[tid] = query[b*HB + tid];
    __syncthreads();
    float a = bq[tid] + br[tid];
    const float* wq = Wq + (size_t)tid * HB;
    #pragma unroll 8
    for (int k = 0; k < HB; ++k) a += qs[k] * wq[k];
    g_qb[b*HB + tid] = a;
}

// ---------------- fused logits: pipelined ldmatrix + mma.sync bf16 ----------------
__global__ void __launch_bounds__(256, 1)
k_logits(const float* __restrict__ ref, const float* __restrict__ V) {
    extern __shared__ char smem[];
    const int tid = threadIdx.x, lane = tid & 31, w = tid >> 5;
    const int wm = w & 3;          // M group: rows wm*32..+31
    const int wn = w >> 2;         // N group: cols wn*64..+63 within a 128-chunk
    const uint32_t sb = s2u(smem);

    float* tbs  = (float*)(smem + TBS_OFF);
    float* Vs   = (float*)(smem + VS_OFF);
    float* lsum = (float*)(smem + LSUM_OFF);

    const long row0 = (long)blockIdx.x * 128;
    const int  b    = (int)(row0 >> 12);

    // ---- X tile: 128 x 512 fp32 -> bf16 smem (padded rows) ----
    const float4* Xg = (const float4*)(ref + row0 * HB);
    #pragma unroll 8
    for (int j = 0; j < 64; ++j) {
        int i = tid + 256*j;
        int r = i >> 7, c4 = i & 127;
        float4 v = Xg[(size_t)r*128 + c4];
        __nv_bfloat162 p0 = __floats2bfloat162_rn(v.x, v.y);
        __nv_bfloat162 p1 = __floats2bfloat162_rn(v.z, v.w);
        uint2 u; u.x = *(uint32_t*)&p0; u.y = *(uint32_t*)&p1;
        *(uint2*)(smem + XS_OFF + ((size_t)r*XLDA + c4*4)*2) = u;
    }
    for (int i = tid; i < HB; i += 256) { tbs[i] = g_qb[b*HB + i]; Vs[i] = V[i]; }
    if (tid < 128) lsum[tid] = 0.f;

    // ---- ldmatrix lane addresses ----
    // A matrices: lanes 0-15 rows m0+(l&15) col kk; 16-31 same rows col kk+8
    const uint32_t a_addr0 = sb + XS_OFF +
        (uint32_t)(((wm*32 + (lane & 15))*XLDA + ((lane >> 4) << 3)) * 2);
    const uint32_t a_addr1 = a_addr0 + 16*XLDA*2;
    // B matrices (per nt-pair ntp): rows n0+((l>>4)<<3)+(l&7), col kk+((l>>3)&1)*8
    uint32_t b_addr[4];
    #pragma unroll
    for (int ntp = 0; ntp < 4; ++ntp)
        b_addr[ntp] = sb + BS_OFF +
            (uint32_t)(((wn*64 + ntp*16 + ((lane >> 4) << 3) + (lane & 7))*WLDA
                        + (((lane >> 3) & 1) << 3)) * 2);

    // ---- stage macro: Wr chunk idx (nc=idx>>3, kb=idx&7) -> buffer idx&1 ----
    #define STAGE(idx_) do {                                                     \
        const int nc_ = (idx_) >> 3, kb_ = (idx_) & 7;                           \
        const uint32_t dstb = sb + BS_OFF + ((idx_) & 1)*BS_BYTES;               \
        const __nv_bfloat16* srcb = g_Wrb + (size_t)(nc_*128)*HB + kb_*64;       \
        _Pragma("unroll")                                                        \
        for (int j_ = 0; j_ < 4; ++j_) {                                         \
            int i_ = tid + 256*j_; int r_ = i_ >> 3, c8_ = i_ & 7;               \
            CPASYNC16(dstb + (uint32_t)((r_*WLDA + c8_*8)*2),                    \
                      srcb + (size_t)r_*HB + c8_*8);                             \
        }                                                                        \
        asm volatile("cp.async.commit_group;" ::: "memory");                     \
    } while (0)

    STAGE(0);

    for (int nc = 0; nc < 4; ++nc) {
        float acc[2][8][4];
        #pragma unroll
        for (int mt = 0; mt < 2; ++mt)
            #pragma unroll
            for (int nt = 0; nt < 8; ++nt)
                #pragma unroll
                for (int i = 0; i < 4; ++i) acc[mt][nt][i] = 0.f;

        for (int kb = 0; kb < 8; ++kb) {
            const int idx = nc*8 + kb;
            asm volatile("cp.async.wait_group 0;" ::: "memory");
            __syncthreads();
            if (idx < 31) STAGE(idx + 1);

            const uint32_t abase = (uint32_t)(kb*128);           // kb*64 elems * 2B
            const uint32_t bbase = (uint32_t)((idx & 1)*BS_BYTES);

            uint32_t af[2][8], bf_[2][16];
            // preload kk=0
            LDSM4(af[0][0],af[0][1],af[0][2],af[0][3], a_addr0 + abase);
            LDSM4(af[0][4],af[0][5],af[0][6],af[0][7], a_addr1 + abase);
            #pragma unroll
            for (int ntp = 0; ntp < 4; ++ntp)
                LDSM4(bf_[0][ntp*4+0],bf_[0][ntp*4+1],bf_[0][ntp*4+2],bf_[0][ntp*4+3],
                      b_addr[ntp] + bbase);

            int cur = 0;
            #pragma unroll
            for (int kk = 0; kk < 4; ++kk) {
                if (kk < 3) {
                    const uint32_t ko = (uint32_t)((kk + 1)*32);
                    LDSM4(af[cur^1][0],af[cur^1][1],af[cur^1][2],af[cur^1][3],
                          a_addr0 + abase + ko);
                    LDSM4(af[cur^1][4],af[cur^1][5],af[cur^1][6],af[cur^1][7],
                          a_addr1 + abase + ko);
                    #pragma unroll
                    for (int ntp = 0; ntp < 4; ++ntp)
                        LDSM4(bf_[cur^1][ntp*4+0],bf_[cur^1][ntp*4+1],
                              bf_[cur^1][ntp*4+2],bf_[cur^1][ntp*4+3],
                              b_addr[ntp] + bbase + ko);
                }
                #pragma unroll
                for (int nt = 0; nt < 8; ++nt) {
                    // ldmatrix x4 register order: R0=b0(even nt), R1=b1(even), R2=b0(odd), R3=b1(odd)
                    const uint32_t b0 = bf_[cur][(nt >> 1)*4 + (nt & 1)*2 + 0];
                    const uint32_t b1 = bf_[cur][(nt >> 1)*4 + (nt & 1)*2 + 1];
                    MMA16816(acc[0][nt], af[cur][0],af[cur][1],af[cur][2],af[cur][3], b0, b1);
                    MMA16816(acc[1][nt], af[cur][4],af[cur][5],af[cur][6],af[cur][7], b0, b1);
                }
                cur ^= 1;
            }
        }

        // ---- epilogue: logits += V[n]*tanh(r + qb[n]) over this 128-col chunk ----
        float rs[2][2] = {{0.f,0.f},{0.f,0.f}};
        #pragma unroll
        for (int mt = 0; mt < 2; ++mt)
            #pragma unroll
            for (int nt = 0; nt < 8; ++nt) {
                const int col0 = nc*128 + wn*64 + nt*8 + ((lane & 3) << 1);
                #pragma unroll
                for (int i = 0; i < 4; ++i) {
                    const int col = col0 + (i & 1);
                    rs[mt][i >> 1] += tanha(acc[mt][nt][i] + tbs[col]) * Vs[col];
                }
            }
        #pragma unroll
        for (int mt = 0; mt < 2; ++mt)
            #pragma unroll
            for (int h = 0; h < 2; ++h) {
                float v = rs[mt][h];
                v += __shfl_xor_sync(0xffffffffu, v, 1);
                v += __shfl_xor_sync(0xffffffffu, v, 2);
                if ((lane & 3) == 0)
                    atomicAdd(&lsum[wm*32 + mt*16 + h*8 + (lane >> 2)], v);
            }
    }

    __syncthreads();
    if (tid < 128) g_logits[row0 + tid] = lsum[tid];
    #undef STAGE
}

// ---------------- softmax: 1 block/batch, 1024 threads, float4 ----------------
__global__ void k_softmax() {
    const int b = blockIdx.x, tid = threadIdx.x;
    __shared__ float red[32];
    __shared__ float bc;
    float4 l = *(const float4*)(g_logits + b*SB + tid*4);
    float m = fmaxf(fmaxf(l.x, l.y), fmaxf(l.z, l.w));
    #pragma unroll
    for (int o = 16; o; o >>= 1) m = fmaxf(m, __shfl_xor_sync(~0u, m, o));
    if ((tid & 31) == 0) red[tid >> 5] = m;
    __syncthreads();
    if (tid < 32) {
        float v = red[tid];
        #pragma unroll
        for (int o = 16; o; o >>= 1) v = fmaxf(v, __shfl_xor_sync(~0u, v, o));
        if (tid == 0) bc = v;
    }
    __syncthreads();
    m = bc;
    float e0 = __expf(l.x - m), e1 = __expf(l.y - m), e2 = __expf(l.z - m), e3 = __expf(l.w - m);
    float s = (e0 + e1) + (e2 + e3);
    #pragma unroll
    for (int o = 16; o; o >>= 1) s += __shfl_xor_sync(~0u, s, o);
    if ((tid & 31) == 0) red[tid >> 5] = s;
    __syncthreads();
    if (tid < 32) {
        float v = red[tid];
        #pragma unroll
        for (int o = 16; o; o >>= 1) v += __shfl_xor_sync(~0u, v, o);
        if (tid == 0) bc = v;
    }
    __syncthreads();
    const float inv = 1.f / bc;
    *(float4*)(g_weights + b*SB + tid*4) = make_float4(e0*inv, e1*inv, e2*inv, e3*inv);
}

// ---------------- weighted ref sum: grid (16, 32), 256 thr, float4 ----------------
__global__ void k_wsum(const float* __restrict__ ref) {
    const int b = blockIdx.y, ch = blockIdx.x;
    const int tid = threadIdx.x;
    __shared__ float ws[256];
    ws[tid] = g_weights[b*SB + ch*256 + tid];
    __syncthreads();
    const int c4 = tid & 127, half = tid >> 7;
    const float4* base = (const float4*)(ref + ((size_t)b*SB + ch*256 + half*128) * HB);
    float4 acc = make_float4(0.f, 0.f, 0.f, 0.f);
    #pragma unroll 4
    for (int s = 0; s < 128; ++s) {
        const float wv = ws[half*128 + s];
        float4 v = base[(size_t)s*128 + c4];
        acc.x += wv*v.x; acc.y += wv*v.y; acc.z += wv*v.z; acc.w += wv*v.w;
    }
    *(float4*)(g_partial + ((size_t)((b*16 + ch)*2 + half))*HB + c4*4) = acc;
}

// ---------------- out[b,h] = (sum partial).Wr[h,:] + br[h] ----------------
__global__ void k_out(const float* __restrict__ Wr, const float* __restrict__ br,
                      float* __restrict__ out) {
    const int b = blockIdx.x, tid = threadIdx.x;   // 32 x 512
    __shared__ float accs[HB];
    float a = 0.f;
    #pragma unroll
    for (int c = 0; c < 32; ++c) a += g_partial[(size_t)(b*32 + c)*HB + tid];
    accs[tid] = a; __syncthreads();
    float o = br[tid];
    const float* wr = Wr + (size_t)tid * HB;
    #pragma unroll 8
    for (int k = 0; k < HB; ++k) o += accs[k] * wr[k];
    out[b*HB + tid] = o;
}

// ---------------- launch ----------------
extern "C" void kernel_launch(void* const* d_in, const int* in_sizes, int n_in,
                              void* d_out, int out_size) {
    const float* query = (const float*)d_in[0];
    const float* ref   = (const float*)d_in[1];
    const float* Wq    = (const float*)d_in[2];
    const float* bq    = (const float*)d_in[3];
    const float* Wr    = (const float*)d_in[4];
    const float* br    = (const float*)d_in[5];
    const float* V     = (const float*)d_in[6];
    float* out = (float*)d_out;

    cudaFuncSetAttribute(k_logits, cudaFuncAttributeMaxDynamicSharedMemorySize, K1_SMEM);

    k_conv   <<<1024, 256>>>(Wr);
    k_qb     <<<BB, 512>>>(query, Wq, bq, br);
    k_logits <<<(BB*SB)/128, 256, K1_SMEM>>>(ref, V);
    k_softmax<<<BB, 1024>>>();
    k_wsum   <<<dim3(16, BB), 256>>>(ref);
    k_out    <<<BB, 512>>>(Wr, br, out);
}